// round 6
// baseline (speedup 1.0000x reference)
#include <cuda_runtime.h>
#include <cstdint>
#include <math.h>

// ---------------- problem constants ----------------
#define TOK   4096
#define RNUM  8
#define DDIM  768
#define FDIM  3072
#define VDIM  2048

// ---------------- device scratch ----------------
__device__ __align__(256) float g_Aperm[(size_t)TOK * DDIM];   // gathered + tf32-rounded activations
__device__ __align__(256) float g_H[(size_t)TOK * FDIM];       // relu(x@W1+b1), permuted, tf32-rounded
__device__ __align__(256) float g_logits[(size_t)TOK * VDIM];  // h@W2+b2, permuted rows
__device__ int g_perm[TOK];
__device__ int g_seg_start[RNUM + 1];

// ---------------- helpers ----------------
__device__ __forceinline__ uint32_t smem_u32(const void* p) {
    return (uint32_t)__cvta_generic_to_shared(p);
}
__device__ __forceinline__ void cp16(uint32_t s, const void* g) {
    asm volatile("cp.async.cg.shared.global [%0], [%1], 16;\n" :: "r"(s), "l"(g));
}
__device__ __forceinline__ uint32_t f2tf32(float x) {
    uint32_t o;
    asm("cvt.rna.tf32.f32 %0, %1;\n" : "=r"(o) : "f"(x));
    return o;
}
__device__ __forceinline__ float round_tf32(float x) {
    return __uint_as_float(f2tf32(x));
}
__device__ __forceinline__ void ldsm4(uint32_t* r, uint32_t addr) {
    asm volatile("ldmatrix.sync.aligned.m8n8.x4.shared.b16 {%0,%1,%2,%3}, [%4];\n"
                 : "=r"(r[0]), "=r"(r[1]), "=r"(r[2]), "=r"(r[3]) : "r"(addr));
}
__device__ __forceinline__ void mma_tf32(float* c, const uint32_t* a, const uint32_t* b) {
    asm volatile(
        "mma.sync.aligned.m16n8k8.row.col.f32.tf32.tf32.f32 "
        "{%0,%1,%2,%3},{%4,%5,%6,%7},{%8,%9},{%0,%1,%2,%3};\n"
        : "+f"(c[0]), "+f"(c[1]), "+f"(c[2]), "+f"(c[3])
        : "r"(a[0]), "r"(a[1]), "r"(a[2]), "r"(a[3]), "r"(b[0]), "r"(b[1]));
}

// ---------------- kernel 1: bucket tokens by route ----------------
__global__ void bucket_kernel(const int* __restrict__ route_ids) {
    __shared__ int s_cnt[RNUM];
    __shared__ int s_cur[RNUM];
    const int t = threadIdx.x;
    if (t < RNUM) s_cnt[t] = 0;
    __syncthreads();
    for (int i = t; i < TOK; i += blockDim.x)
        atomicAdd(&s_cnt[route_ids[i]], 1);
    __syncthreads();
    if (t == 0) {
        int off = 0;
        for (int r = 0; r < RNUM; r++) {
            g_seg_start[r] = off;
            s_cur[r] = off;
            off += s_cnt[r];
        }
        g_seg_start[RNUM] = off;
    }
    __syncthreads();
    for (int i = t; i < TOK; i += blockDim.x) {
        int r = route_ids[i];
        int pos = atomicAdd(&s_cur[r], 1);
        g_perm[pos] = i;
    }
}

// ---------------- kernel 2: gather A rows by perm, round to tf32 ----------------
__global__ __launch_bounds__(192)
void gather_kernel(const float* __restrict__ e_two) {
    const int row = blockIdx.x;
    const int tok = g_perm[row];
    const float4* src = reinterpret_cast<const float4*>(e_two + (size_t)tok * DDIM);
    float4* dst = reinterpret_cast<float4*>(g_Aperm + (size_t)row * DDIM);
    float4 v = src[threadIdx.x];
    v.x = round_tf32(v.x); v.y = round_tf32(v.y);
    v.z = round_tf32(v.z); v.w = round_tf32(v.w);
    dst[threadIdx.x] = v;
}

// ---------------- tf32 GEMM, occupancy-optimized ----------------
// CTA tile 128(m) x 64(n), BK=16, 3-stage cp.async pipeline, static smem 44.5KB,
// ~80 regs -> 3 CTAs/SM (24 warps). 8 warps: 4(m) x 2(n), warp tile 32x32.
// A fragments via ldmatrix.x4 (A pre-rounded tf32); B via scalar LDS + cvt
// with conflict-free stride 72.
static constexpr int BK = 16;
static constexpr int BN = 64;
static constexpr int SA_STRIDE = 20;                 // 16 + 4 pad floats
static constexpr int SB_STRIDE = 72;                 // 64 + 8 pad floats (8*72%32 spread)
static constexpr int SA_FLOATS = 128 * SA_STRIDE;    // 2560 per stage
static constexpr int SB_FLOATS = BK * SB_STRIDE;     // 1152 per stage
static constexpr int STAGE_FLOATS = SA_FLOATS + SB_FLOATS;   // 3712
static constexpr int NSTAGE = 3;

template <int KTOT, int NTOT, bool RELU>
__global__ void __launch_bounds__(256, 3)
gemm_occ(const float* __restrict__ Abase,
         const float* __restrict__ Bbase,
         const float* __restrict__ biasBase,
         float* __restrict__ Cbase) {
    constexpr int NK = KTOT / BK;

    __shared__ float smem[NSTAGE * STAGE_FLOATS];    // 44,544 B static

    const int r    = blockIdx.z;
    const int seg0 = g_seg_start[r];
    const int cnt  = g_seg_start[r + 1] - seg0;
    const int m0   = blockIdx.y * 128;
    if (m0 >= cnt) return;
    const int n0 = blockIdx.x * BN;

    const float* B    = Bbase + (size_t)r * (size_t)KTOT * NTOT;
    const float* bias = biasBase + (size_t)r * NTOT;

    const int tid  = threadIdx.x;
    const int warp = tid >> 5;
    const int lane = tid & 31;
    const int wm = warp & 3;    // 4 warp-rows of 32
    const int wn = warp >> 2;   // 2 warp-cols of 32
    const int lg = lane >> 2;
    const int lt = lane & 3;

    // loader: A 128x16 floats (512 16B chunks -> 2/thread), B 16x64 (256 -> 1/thread)
    const int a_ldrow = tid >> 2;        // 0..63 (x2 blocks)
    const int a_ldch  = tid & 3;
    const int b_ldrow = tid >> 4;        // 0..15
    const int b_ldch  = tid & 15;
    auto load_tile = [&](int kt, int buf) {
        const int k0 = kt * BK;
        float* dA = smem + buf * STAGE_FLOATS;
        float* dB = dA + SA_FLOATS;
        #pragma unroll
        for (int i = 0; i < 2; i++) {
            int row = a_ldrow + i * 64;
            int grow = seg0 + m0 + row;
            if (grow > TOK - 1) grow = TOK - 1;     // clamp; stores guarded
            cp16(smem_u32(dA + row * SA_STRIDE + a_ldch * 4),
                 Abase + (size_t)grow * KTOT + k0 + a_ldch * 4);
        }
        cp16(smem_u32(dB + b_ldrow * SB_STRIDE + b_ldch * 4),
             B + (size_t)(k0 + b_ldrow) * NTOT + n0 + b_ldch * 4);
        asm volatile("cp.async.commit_group;\n");
    };

    float acc[2][4][4];
    #pragma unroll
    for (int mt = 0; mt < 2; mt++)
        #pragma unroll
        for (int nt = 0; nt < 4; nt++)
            #pragma unroll
            for (int j = 0; j < 4; j++) acc[mt][nt][j] = 0.f;

    // ldmatrix A lane address (bytes within a stage buffer)
    const int a_row = wm * 32 + (lane & 7) + (((lane >> 3) & 1) << 3);
    const int a_colb = (((lane >> 4) & 1) << 4);
    const uint32_t aBase = smem_u32(smem) + (uint32_t)(a_row * SA_STRIDE * 4 + a_colb);

    load_tile(0, 0);
    load_tile(1, 1);

    for (int kt = 0; kt < NK; kt++) {
        const int buf = kt % NSTAGE;
        asm volatile("cp.async.wait_group 1;\n");   // group kt complete (this thread)
        __syncthreads();                            // ...for all threads; buf (kt+2)%3 free
        if (kt + 2 < NK) load_tile(kt + 2, (kt + 2) % NSTAGE);
        else asm volatile("cp.async.commit_group;\n");   // keep group accounting exact

        const uint32_t aBuf = aBase + buf * (STAGE_FLOATS * 4);
        const float*   bBuf = smem + buf * STAGE_FLOATS + SA_FLOATS;

        #pragma unroll
        for (int ks = 0; ks < 2; ks++) {
            uint32_t afr[2][4];
            #pragma unroll
            for (int mt = 0; mt < 2; mt++)
                ldsm4(afr[mt], aBuf + mt * (16 * SA_STRIDE * 4) + ks * 32);

            uint32_t bfr[4][2];
            const int kb = ks * 8 + lt;
            #pragma unroll
            for (int nt = 0; nt < 4; nt++) {
                const int cc = wn * 32 + nt * 8 + lg;
                bfr[nt][0] = f2tf32(bBuf[kb * SB_STRIDE + cc]);
                bfr[nt][1] = f2tf32(bBuf[(kb + 4) * SB_STRIDE + cc]);
            }
            #pragma unroll
            for (int mt = 0; mt < 2; mt++)
                #pragma unroll
                for (int nt = 0; nt < 4; nt++)
                    mma_tf32(acc[mt][nt], afr[mt], bfr[nt]);
        }
    }

    __syncthreads();

    // epilogue: bias (+relu+tf32-round for phase1), guarded float2 stores
    #pragma unroll
    for (int mt = 0; mt < 2; mt++) {
        #pragma unroll
        for (int half = 0; half < 2; half++) {
            const int rowl = wm * 32 + mt * 16 + lg + half * 8;
            const int mrow = m0 + rowl;
            if (mrow < cnt) {
                float* crow = Cbase + (size_t)(seg0 + mrow) * NTOT;
                #pragma unroll
                for (int nt = 0; nt < 4; nt++) {
                    const int col = n0 + wn * 32 + nt * 8 + lt * 2;
                    float v0 = acc[mt][nt][half * 2 + 0] + bias[col];
                    float v1 = acc[mt][nt][half * 2 + 1] + bias[col + 1];
                    if (RELU) {
                        v0 = round_tf32(fmaxf(v0, 0.f));
                        v1 = round_tf32(fmaxf(v1, 0.f));
                    }
                    *reinterpret_cast<float2*>(crow + col) = make_float2(v0, v1);
                }
            }
        }
    }
}

// ---------------- softmax + scatter to real token rows ----------------
__global__ __launch_bounds__(256)
void softmax_kernel(float* __restrict__ out) {
    const int i   = blockIdx.x;
    const int tok = g_perm[i];
    const float* lrow = g_logits + (size_t)i * VDIM;
    float*       orow = out + (size_t)tok * VDIM;
    const int tid = threadIdx.x;

    float v[8];
    float mx = -1e30f;
    #pragma unroll
    for (int j = 0; j < 8; j++) {
        v[j] = lrow[tid + 256 * j];
        mx = fmaxf(mx, v[j]);
    }
    #pragma unroll
    for (int o = 16; o; o >>= 1) mx = fmaxf(mx, __shfl_xor_sync(0xffffffffu, mx, o));

    __shared__ float sred[8];
    const int w = tid >> 5;
    if ((tid & 31) == 0) sred[w] = mx;
    __syncthreads();
    float bmx = sred[0];
    #pragma unroll
    for (int j = 1; j < 8; j++) bmx = fmaxf(bmx, sred[j]);

    float s = 0.f;
    #pragma unroll
    for (int j = 0; j < 8; j++) {
        v[j] = expf(v[j] - bmx);
        s += v[j];
    }
    #pragma unroll
    for (int o = 16; o; o >>= 1) s += __shfl_xor_sync(0xffffffffu, s, o);
    __syncthreads();
    if ((tid & 31) == 0) sred[w] = s;
    __syncthreads();
    float tot = 0.f;
    #pragma unroll
    for (int j = 0; j < 8; j++) tot += sred[j];
    const float inv = 1.f / tot;
    #pragma unroll
    for (int j = 0; j < 8; j++) orow[tid + 256 * j] = v[j] * inv;
}

// ---------------- launch ----------------
extern "C" void kernel_launch(void* const* d_in, const int* in_sizes, int n_in,
                              void* d_out, int out_size) {
    const float* e_two     = (const float*)d_in[0];   // [4,1024,768]
    const int*   route_ids = (const int*)d_in[1];     // [4,1024]
    const float* W1        = (const float*)d_in[2];   // [8,768,3072]
    const float* b1        = (const float*)d_in[3];   // [8,3072]
    const float* W2        = (const float*)d_in[4];   // [8,3072,2048]
    const float* b2        = (const float*)d_in[5];   // [8,2048]
    float*       out       = (float*)d_out;           // [4,1024,2048]

    void *pA, *pH, *pL;
    cudaGetSymbolAddress(&pA, g_Aperm);
    cudaGetSymbolAddress(&pH, g_H);
    cudaGetSymbolAddress(&pL, g_logits);

    bucket_kernel<<<1, 512>>>(route_ids);
    gather_kernel<<<TOK, 192>>>(e_two);

    dim3 g1(FDIM / BN, TOK / 128, RNUM);   // (48, 32, 8)
    gemm_occ<DDIM, FDIM, true><<<g1, 256>>>(
        (const float*)pA, W1, b1, (float*)pH);

    dim3 g2(VDIM / BN, TOK / 128, RNUM);   // (32, 32, 8)
    gemm_occ<FDIM, VDIM, false><<<g2, 256>>>(
        (const float*)pH, W2, b2, (float*)pL);

    softmax_kernel<<<TOK, 256>>>(out);
}

// round 7
// speedup vs baseline: 1.2965x; 1.2965x over previous
#include <cuda_runtime.h>
#include <cstdint>
#include <math.h>

// ---------------- problem constants ----------------
#define TOK   4096
#define RNUM  8
#define DDIM  768
#define FDIM  3072
#define VDIM  2048

// ---------------- device scratch ----------------
__device__ __align__(256) float g_Aperm[(size_t)TOK * DDIM];   // gathered + tf32-rounded activations
__device__ __align__(256) float g_H[(size_t)TOK * FDIM];       // relu(x@W1+b1), permuted, tf32-rounded
__device__ __align__(256) float g_logits[(size_t)TOK * VDIM];  // h@W2+b2, permuted rows
__device__ int g_perm[TOK];
__device__ int g_seg_start[RNUM + 1];

// ---------------- helpers ----------------
__device__ __forceinline__ uint32_t smem_u32(const void* p) {
    return (uint32_t)__cvta_generic_to_shared(p);
}
__device__ __forceinline__ void cp16(uint32_t s, const void* g) {
    asm volatile("cp.async.cg.shared.global [%0], [%1], 16;\n" :: "r"(s), "l"(g));
}
__device__ __forceinline__ uint32_t f2tf32(float x) {
    uint32_t o;
    asm("cvt.rna.tf32.f32 %0, %1;\n" : "=r"(o) : "f"(x));
    return o;
}
__device__ __forceinline__ float round_tf32(float x) {
    return __uint_as_float(f2tf32(x));
}
__device__ __forceinline__ void ldsm4(uint32_t* r, uint32_t addr) {
    asm volatile("ldmatrix.sync.aligned.m8n8.x4.shared.b16 {%0,%1,%2,%3}, [%4];\n"
                 : "=r"(r[0]), "=r"(r[1]), "=r"(r[2]), "=r"(r[3]) : "r"(addr));
}
__device__ __forceinline__ void mma_tf32(float* c, const uint32_t* a, const uint32_t* b) {
    asm volatile(
        "mma.sync.aligned.m16n8k8.row.col.f32.tf32.tf32.f32 "
        "{%0,%1,%2,%3},{%4,%5,%6,%7},{%8,%9},{%0,%1,%2,%3};\n"
        : "+f"(c[0]), "+f"(c[1]), "+f"(c[2]), "+f"(c[3])
        : "r"(a[0]), "r"(a[1]), "r"(a[2]), "r"(a[3]), "r"(b[0]), "r"(b[1]));
}

// ---------------- kernel 1: bucket tokens by route ----------------
__global__ void bucket_kernel(const int* __restrict__ route_ids) {
    __shared__ int s_cnt[RNUM];
    __shared__ int s_cur[RNUM];
    const int t = threadIdx.x;
    if (t < RNUM) s_cnt[t] = 0;
    __syncthreads();
    for (int i = t; i < TOK; i += blockDim.x)
        atomicAdd(&s_cnt[route_ids[i]], 1);
    __syncthreads();
    if (t == 0) {
        int off = 0;
        for (int r = 0; r < RNUM; r++) {
            g_seg_start[r] = off;
            s_cur[r] = off;
            off += s_cnt[r];
        }
        g_seg_start[RNUM] = off;
    }
    __syncthreads();
    for (int i = t; i < TOK; i += blockDim.x) {
        int r = route_ids[i];
        int pos = atomicAdd(&s_cur[r], 1);
        g_perm[pos] = i;
    }
}

// ---------------- kernel 2: gather A rows by perm, round to tf32 ----------------
__global__ __launch_bounds__(192)
void gather_kernel(const float* __restrict__ e_two) {
    const int row = blockIdx.x;
    const int tok = g_perm[row];
    const float4* src = reinterpret_cast<const float4*>(e_two + (size_t)tok * DDIM);
    float4* dst = reinterpret_cast<float4*>(g_Aperm + (size_t)row * DDIM);
    float4 v = src[threadIdx.x];
    v.x = round_tf32(v.x); v.y = round_tf32(v.y);
    v.z = round_tf32(v.z); v.w = round_tf32(v.w);
    dst[threadIdx.x] = v;
}

// ---------------- tf32 GEMM: 4 warps, 64x64 warp tiles (smem-traffic optimized) ----
// CTA tile 128x128, BK=32, 2-stage cp.async double buffer (R3-proven pipeline).
// 4 warps (128 thr): 2(m) x 2(n), warp tile 64x64 -> smem traffic 96KB per K-slab
// (vs 128KB with 8x 64x32 warps) => tensor no longer port-bound.
// A fragments via ldmatrix.x4 (pre-rounded tf32); B scalar LDS + cvt.
static constexpr int BK = 32;
static constexpr int SA_STRIDE = 36;    // 32 + 4 pad floats
static constexpr int SB_STRIDE = 132;   // 128 + 4 pad
static constexpr int SA_FLOATS = 128 * SA_STRIDE;   // per stage
static constexpr int SB_FLOATS = BK * SB_STRIDE;    // per stage
static constexpr int SMEM_BYTES = 2 * (SA_FLOATS + SB_FLOATS) * 4;   // 70,656 B

template <int KTOT, int NTOT, bool RELU>
__global__ void __launch_bounds__(128, 2)
gemm_w64(const float* __restrict__ Abase,
         const float* __restrict__ Bbase,
         const float* __restrict__ biasBase,
         float* __restrict__ Cbase) {
    constexpr int NK = KTOT / BK;

    extern __shared__ float smem[];
    float* sA = smem;                       // [2][128][SA_STRIDE]
    float* sB = smem + 2 * SA_FLOATS;       // [2][BK][SB_STRIDE]

    const int r    = blockIdx.z;
    const int seg0 = g_seg_start[r];
    const int cnt  = g_seg_start[r + 1] - seg0;
    const int m0   = blockIdx.y * 128;
    if (m0 >= cnt) return;
    const int n0 = blockIdx.x * 128;

    const float* B    = Bbase + (size_t)r * (size_t)KTOT * NTOT;
    const float* bias = biasBase + (size_t)r * NTOT;

    const int tid  = threadIdx.x;
    const int warp = tid >> 5;
    const int lane = tid & 31;
    const int wm = warp & 1;    // 2 warp-rows of 64
    const int wn = warp >> 1;   // 2 warp-cols of 64
    const int lg = lane >> 2;
    const int lt = lane & 3;

    // loader (128 threads): A 128x32 floats = 1024 chunks (8/thr), B 32x128 = 1024 (8/thr)
    auto load_tile = [&](int kt, int buf) {
        const int k0 = kt * BK;
        float* dA = sA + buf * SA_FLOATS;
        float* dB = sB + buf * SB_FLOATS;
        #pragma unroll
        for (int i = 0; i < 8; i++) {
            int idx = tid + i * 128;
            int row = idx >> 3;          // 0..127
            int ch  = idx & 7;
            int grow = seg0 + m0 + row;
            if (grow > TOK - 1) grow = TOK - 1;   // clamp; stores guarded
            cp16(smem_u32(dA + row * SA_STRIDE + ch * 4),
                 Abase + (size_t)grow * KTOT + k0 + ch * 4);
        }
        #pragma unroll
        for (int i = 0; i < 8; i++) {
            int idx = tid + i * 128;
            int row = idx >> 5;          // 0..31
            int ch  = idx & 31;
            cp16(smem_u32(dB + row * SB_STRIDE + ch * 4),
                 B + (size_t)(k0 + row) * NTOT + n0 + ch * 4);
        }
        asm volatile("cp.async.commit_group;\n");
    };

    float acc[4][8][4];
    #pragma unroll
    for (int mt = 0; mt < 4; mt++)
        #pragma unroll
        for (int nt = 0; nt < 8; nt++)
            #pragma unroll
            for (int j = 0; j < 4; j++) acc[mt][nt][j] = 0.f;

    // ldmatrix A lane address (bytes within an A stage buffer)
    const int a_row = wm * 64 + (lane & 7) + (((lane >> 3) & 1) << 3);
    const int a_colb = (((lane >> 4) & 1) << 4);
    const uint32_t aBase = smem_u32(sA) + (uint32_t)(a_row * SA_STRIDE * 4 + a_colb);

    load_tile(0, 0);

    for (int kt = 0; kt < NK; kt++) {
        const int buf = kt & 1;
        if (kt + 1 < NK) {
            load_tile(kt + 1, buf ^ 1);
            asm volatile("cp.async.wait_group 1;\n");
        } else {
            asm volatile("cp.async.wait_group 0;\n");
        }
        __syncthreads();

        const uint32_t aBuf = aBase + buf * (SA_FLOATS * 4);
        const float*   bBuf = sB + buf * SB_FLOATS;

        #pragma unroll
        for (int ks = 0; ks < 4; ks++) {
            uint32_t afr[4][4];
            #pragma unroll
            for (int mt = 0; mt < 4; mt++)
                ldsm4(afr[mt], aBuf + mt * (16 * SA_STRIDE * 4) + ks * 32);

            uint32_t bfr[8][2];
            const int kb = ks * 8 + lt;
            #pragma unroll
            for (int nt = 0; nt < 8; nt++) {
                const int cc = wn * 64 + nt * 8 + lg;
                bfr[nt][0] = f2tf32(bBuf[kb * SB_STRIDE + cc]);
                bfr[nt][1] = f2tf32(bBuf[(kb + 4) * SB_STRIDE + cc]);
            }
            #pragma unroll
            for (int mt = 0; mt < 4; mt++)
                #pragma unroll
                for (int nt = 0; nt < 8; nt++)
                    mma_tf32(acc[mt][nt], afr[mt], bfr[nt]);
        }
        __syncthreads();
    }

    // epilogue: bias (+relu+tf32-round for phase1), guarded float2 stores
    #pragma unroll
    for (int mt = 0; mt < 4; mt++) {
        #pragma unroll
        for (int half = 0; half < 2; half++) {
            const int rowl = wm * 64 + mt * 16 + lg + half * 8;
            const int mrow = m0 + rowl;
            if (mrow < cnt) {
                float* crow = Cbase + (size_t)(seg0 + mrow) * NTOT;
                #pragma unroll
                for (int nt = 0; nt < 8; nt++) {
                    const int col = n0 + wn * 64 + nt * 8 + lt * 2;
                    float v0 = acc[mt][nt][half * 2 + 0] + bias[col];
                    float v1 = acc[mt][nt][half * 2 + 1] + bias[col + 1];
                    if (RELU) {
                        v0 = round_tf32(fmaxf(v0, 0.f));
                        v1 = round_tf32(fmaxf(v1, 0.f));
                    }
                    *reinterpret_cast<float2*>(crow + col) = make_float2(v0, v1);
                }
            }
        }
    }
}

// ---------------- softmax + scatter to real token rows ----------------
__global__ __launch_bounds__(256)
void softmax_kernel(float* __restrict__ out) {
    const int i   = blockIdx.x;
    const int tok = g_perm[i];
    const float* lrow = g_logits + (size_t)i * VDIM;
    float*       orow = out + (size_t)tok * VDIM;
    const int tid = threadIdx.x;

    float v[8];
    float mx = -1e30f;
    #pragma unroll
    for (int j = 0; j < 8; j++) {
        v[j] = lrow[tid + 256 * j];
        mx = fmaxf(mx, v[j]);
    }
    #pragma unroll
    for (int o = 16; o; o >>= 1) mx = fmaxf(mx, __shfl_xor_sync(0xffffffffu, mx, o));

    __shared__ float sred[8];
    const int w = tid >> 5;
    if ((tid & 31) == 0) sred[w] = mx;
    __syncthreads();
    float bmx = sred[0];
    #pragma unroll
    for (int j = 1; j < 8; j++) bmx = fmaxf(bmx, sred[j]);

    float s = 0.f;
    #pragma unroll
    for (int j = 0; j < 8; j++) {
        v[j] = expf(v[j] - bmx);
        s += v[j];
    }
    #pragma unroll
    for (int o = 16; o; o >>= 1) s += __shfl_xor_sync(0xffffffffu, s, o);
    __syncthreads();
    if ((tid & 31) == 0) sred[w] = s;
    __syncthreads();
    float tot = 0.f;
    #pragma unroll
    for (int j = 0; j < 8; j++) tot += sred[j];
    const float inv = 1.f / tot;
    #pragma unroll
    for (int j = 0; j < 8; j++) orow[tid + 256 * j] = v[j] * inv;
}

// ---------------- launch ----------------
extern "C" void kernel_launch(void* const* d_in, const int* in_sizes, int n_in,
                              void* d_out, int out_size) {
    const float* e_two     = (const float*)d_in[0];   // [4,1024,768]
    const int*   route_ids = (const int*)d_in[1];     // [4,1024]
    const float* W1        = (const float*)d_in[2];   // [8,768,3072]
    const float* b1        = (const float*)d_in[3];   // [8,3072]
    const float* W2        = (const float*)d_in[4];   // [8,3072,2048]
    const float* b2        = (const float*)d_in[5];   // [8,2048]
    float*       out       = (float*)d_out;           // [4,1024,2048]

    void *pA, *pH, *pL;
    cudaGetSymbolAddress(&pA, g_Aperm);
    cudaGetSymbolAddress(&pH, g_H);
    cudaGetSymbolAddress(&pL, g_logits);

    static bool attr_done = false;
    if (!attr_done) {
        cudaFuncSetAttribute(gemm_w64<DDIM, FDIM, true>,
                             cudaFuncAttributeMaxDynamicSharedMemorySize, SMEM_BYTES);
        cudaFuncSetAttribute(gemm_w64<FDIM, VDIM, false>,
                             cudaFuncAttributeMaxDynamicSharedMemorySize, SMEM_BYTES);
        attr_done = true;
    }

    bucket_kernel<<<1, 512>>>(route_ids);
    gather_kernel<<<TOK, 192>>>(e_two);

    dim3 g1(FDIM / 128, TOK / 128, RNUM);   // (24, 32, 8)
    gemm_w64<DDIM, FDIM, true><<<g1, 128, SMEM_BYTES>>>(
        (const float*)pA, W1, b1, (float*)pH);

    dim3 g2(VDIM / 128, TOK / 128, RNUM);   // (16, 32, 8)
    gemm_w64<FDIM, VDIM, false><<<g2, 128, SMEM_BYTES>>>(
        (const float*)pH, W2, b2, (float*)pL);

    softmax_kernel<<<TOK, 256>>>(out);
}

// round 8
// speedup vs baseline: 1.4026x; 1.0818x over previous
#include <cuda_runtime.h>
#include <cstdint>
#include <math.h>

// ---------------- problem constants ----------------
#define TOK   4096
#define RNUM  8
#define DDIM  768
#define FDIM  3072
#define VDIM  2048

// ---------------- device scratch ----------------
__device__ __align__(256) float g_Aperm[(size_t)TOK * DDIM];   // gathered + tf32-rounded activations
__device__ __align__(256) float g_H[(size_t)TOK * FDIM];       // relu(x@W1+b1), permuted, tf32-rounded
__device__ __align__(256) float g_logits[(size_t)TOK * VDIM];  // h@W2+b2, permuted rows
__device__ int g_perm[TOK];
__device__ int g_seg_start[RNUM + 1];

// ---------------- helpers ----------------
__device__ __forceinline__ uint32_t smem_u32(const void* p) {
    return (uint32_t)__cvta_generic_to_shared(p);
}
__device__ __forceinline__ void cp16(uint32_t s, const void* g) {
    asm volatile("cp.async.cg.shared.global [%0], [%1], 16;\n" :: "r"(s), "l"(g));
}
__device__ __forceinline__ uint32_t f2tf32(float x) {
    uint32_t o;
    asm("cvt.rna.tf32.f32 %0, %1;\n" : "=r"(o) : "f"(x));
    return o;
}
__device__ __forceinline__ float round_tf32(float x) {
    return __uint_as_float(f2tf32(x));
}
__device__ __forceinline__ void ldsm4(uint32_t* r, uint32_t addr) {
    asm volatile("ldmatrix.sync.aligned.m8n8.x4.shared.b16 {%0,%1,%2,%3}, [%4];\n"
                 : "=r"(r[0]), "=r"(r[1]), "=r"(r[2]), "=r"(r[3]) : "r"(addr));
}
__device__ __forceinline__ void mma_tf32(float* c, const uint32_t* a, const uint32_t* b) {
    asm volatile(
        "mma.sync.aligned.m16n8k8.row.col.f32.tf32.tf32.f32 "
        "{%0,%1,%2,%3},{%4,%5,%6,%7},{%8,%9},{%0,%1,%2,%3};\n"
        : "+f"(c[0]), "+f"(c[1]), "+f"(c[2]), "+f"(c[3])
        : "r"(a[0]), "r"(a[1]), "r"(a[2]), "r"(a[3]), "r"(b[0]), "r"(b[1]));
}

// ---------------- kernel 1: bucket tokens by route ----------------
__global__ void bucket_kernel(const int* __restrict__ route_ids) {
    __shared__ int s_cnt[RNUM];
    __shared__ int s_cur[RNUM];
    const int t = threadIdx.x;
    if (t < RNUM) s_cnt[t] = 0;
    __syncthreads();
    for (int i = t; i < TOK; i += blockDim.x)
        atomicAdd(&s_cnt[route_ids[i]], 1);
    __syncthreads();
    if (t == 0) {
        int off = 0;
        for (int r = 0; r < RNUM; r++) {
            g_seg_start[r] = off;
            s_cur[r] = off;
            off += s_cnt[r];
        }
        g_seg_start[RNUM] = off;
    }
    __syncthreads();
    for (int i = t; i < TOK; i += blockDim.x) {
        int r = route_ids[i];
        int pos = atomicAdd(&s_cur[r], 1);
        g_perm[pos] = i;
    }
}

// ---------------- kernel 2: gather A rows by perm, round to tf32 ----------------
__global__ __launch_bounds__(192)
void gather_kernel(const float* __restrict__ e_two) {
    const int row = blockIdx.x;
    const int tok = g_perm[row];
    const float4* src = reinterpret_cast<const float4*>(e_two + (size_t)tok * DDIM);
    float4* dst = reinterpret_cast<float4*>(g_Aperm + (size_t)row * DDIM);
    float4 v = src[threadIdx.x];
    v.x = round_tf32(v.x); v.y = round_tf32(v.y);
    v.z = round_tf32(v.z); v.w = round_tf32(v.w);
    dst[threadIdx.x] = v;
}

// ---------------- tf32 GEMM: dual-ldmatrix with in-kernel B transpose ----------------
// C[128x128] = A[128 x K] @ B[K x 128] (+bias, optional relu+round)
// A: 3-stage cp.async + ldmatrix (proven R5 pipeline ordering, 1 barrier/kt).
// B: per-thread column LDG (lane<->n, coalesced) -> cvt.rna.tf32 in regs ->
//    STS.128 row of smem-Bt[n][k] (conflict-free phases) -> ldmatrix fragments
//    (R5-proven mapping). No LDS-latency chain, no in-loop cvt.
// 4 warps (128 thr): 2(m) x 2(n), warp tile 64x64. 2 CTAs/SM.
static constexpr int BK = 32;
static constexpr int TSTRIDE = 36;                       // 32 + 4 pad floats
static constexpr int TILE_FLOATS = 128 * TSTRIDE;        // 4608 floats per tile
static constexpr int ASTAGES = 3;
static constexpr int SMEM_BYTES = (ASTAGES + 2) * TILE_FLOATS * 4;   // 92,160 B

template <int KTOT, int NTOT, bool RELU>
__global__ void __launch_bounds__(128, 2)
gemm_dlt(const float* __restrict__ Abase,
         const float* __restrict__ Bbase,
         const float* __restrict__ biasBase,
         float* __restrict__ Cbase) {
    constexpr int NK = KTOT / BK;

    extern __shared__ float smem[];
    float* sA  = smem;                        // [3][128][36]
    float* sBt = smem + ASTAGES * TILE_FLOATS; // [2][128][36]  (row = n, col = k)

    const int r    = blockIdx.z;
    const int seg0 = g_seg_start[r];
    const int cnt  = g_seg_start[r + 1] - seg0;
    const int m0   = blockIdx.y * 128;
    if (m0 >= cnt) return;
    const int n0 = blockIdx.x * 128;

    const float* B    = Bbase + (size_t)r * (size_t)KTOT * NTOT;
    const float* bias = biasBase + (size_t)r * NTOT;

    const int tid  = threadIdx.x;
    const int warp = tid >> 5;
    const int lane = tid & 31;
    const int wm = warp & 1;    // 2 warp-rows of 64
    const int wn = warp >> 1;   // 2 warp-cols of 64
    const int lg = lane >> 2;
    const int lt = lane & 3;

    // ---- A loader: 128x32 floats = 1024 16B chunks, 8 per thread, cp.async ----
    auto loadA = [&](int kt, int buf) {
        const int k0 = kt * BK;
        float* dA = sA + buf * TILE_FLOATS;
        #pragma unroll
        for (int i = 0; i < 8; i++) {
            int idx = tid + i * 128;
            int row = idx >> 3;
            int ch  = idx & 7;
            int grow = seg0 + m0 + row;
            if (grow > TOK - 1) grow = TOK - 1;     // clamp; stores guarded
            cp16(smem_u32(dA + row * TSTRIDE + ch * 4),
                 Abase + (size_t)grow * KTOT + k0 + ch * 4);
        }
        asm volatile("cp.async.commit_group;\n");
    };

    // ---- B staging: thread tid owns column n = n0+tid of the B tile ----
    const float* bCol = B + n0 + tid;            // + k*NTOT indexes rows
    float rawB[BK];                              // raw fp32 column for tile kt
    auto ldgB = [&](int kt) {
        const int k0 = kt * BK;
        #pragma unroll
        for (int j = 0; j < BK; j++)
            rawB[j] = __ldg(bCol + (size_t)(k0 + j) * NTOT);
    };
    auto stsB = [&](int buf) {                   // round + store row n=tid of sBt
        float* dst = sBt + buf * TILE_FLOATS + tid * TSTRIDE;
        #pragma unroll
        for (int j = 0; j < BK; j += 4) {
            float4 v;
            v.x = round_tf32(rawB[j + 0]);
            v.y = round_tf32(rawB[j + 1]);
            v.z = round_tf32(rawB[j + 2]);
            v.w = round_tf32(rawB[j + 3]);
            *reinterpret_cast<float4*>(dst + j) = v;
        }
    };

    float acc[4][8][4];
    #pragma unroll
    for (int mt = 0; mt < 4; mt++)
        #pragma unroll
        for (int nt = 0; nt < 8; nt++)
            #pragma unroll
            for (int j = 0; j < 4; j++) acc[mt][nt][j] = 0.f;

    // ldmatrix lane addresses (bytes within a tile buffer)
    // A (row-major m x k): proven mapping
    const int a_row = wm * 64 + (lane & 7) + (((lane >> 3) & 1) << 3);
    const int a_colb = (((lane >> 4) & 1) << 4);
    const uint32_t aBase = smem_u32(sA) + (uint32_t)(a_row * TSTRIDE * 4 + a_colb);
    // B (Bt rows = n, cols = k): R5-proven mapping
    const int b_row = wn * 64 + (lane & 7) + (((lane >> 4) & 1) << 3);
    const int b_colb = (((lane >> 3) & 1) << 4);
    const uint32_t bBase = smem_u32(sBt) + (uint32_t)(b_row * TSTRIDE * 4 + b_colb);

    // ---- prologue ----
    loadA(0, 0);                 // group: A0
    loadA(1, 1);                 // group: A1
    ldgB(0);
    stsB(0);                     // sBt[0] = B(0); no readers yet
    if (NK > 1) ldgB(1);         // rawB = B(1)

    for (int kt = 0; kt < NK; kt++) {
        const int abuf = kt % ASTAGES;
        const int bbuf = kt & 1;
        // A(kt) complete for this thread (pending = {kt, kt+1} before wait)
        asm volatile("cp.async.wait_group 1;\n");
        // ...for all threads; STS of sBt[bbuf] visible; stage buffers from kt-1 free
        __syncthreads();

        if (kt + 1 < NK) stsB(bbuf ^ 1);                 // sBt[(kt+1)&1] = B(kt+1)
        if (kt + 2 < NK) {
            ldgB(kt + 2);                                // rawB = B(kt+2)
            loadA(kt + 2, (kt + 2) % ASTAGES);           // commit A(kt+2)
        } else {
            asm volatile("cp.async.commit_group;\n");    // keep group accounting exact
        }

        const uint32_t aBuf = aBase + abuf * (TILE_FLOATS * 4);
        const uint32_t bBuf = bBase + bbuf * (TILE_FLOATS * 4);

        #pragma unroll
        for (int ks = 0; ks < 4; ks++) {
            uint32_t afr[4][4];
            #pragma unroll
            for (int mt = 0; mt < 4; mt++)
                ldsm4(afr[mt], aBuf + mt * (16 * TSTRIDE * 4) + ks * 32);

            uint32_t bfr[8][2];
            #pragma unroll
            for (int ntp = 0; ntp < 4; ntp++) {
                uint32_t q[4];
                ldsm4(q, bBuf + ntp * (16 * TSTRIDE * 4) + ks * 32);
                bfr[2 * ntp + 0][0] = q[0];
                bfr[2 * ntp + 0][1] = q[1];
                bfr[2 * ntp + 1][0] = q[2];
                bfr[2 * ntp + 1][1] = q[3];
            }
            #pragma unroll
            for (int mt = 0; mt < 4; mt++)
                #pragma unroll
                for (int nt = 0; nt < 8; nt++)
                    mma_tf32(acc[mt][nt], afr[mt], bfr[nt]);
        }
    }

    __syncthreads();

    // epilogue: bias (+relu+tf32-round for phase1), guarded float2 stores
    #pragma unroll
    for (int mt = 0; mt < 4; mt++) {
        #pragma unroll
        for (int half = 0; half < 2; half++) {
            const int rowl = wm * 64 + mt * 16 + lg + half * 8;
            const int mrow = m0 + rowl;
            if (mrow < cnt) {
                float* crow = Cbase + (size_t)(seg0 + mrow) * NTOT;
                #pragma unroll
                for (int nt = 0; nt < 8; nt++) {
                    const int col = n0 + wn * 64 + nt * 8 + lt * 2;
                    float v0 = acc[mt][nt][half * 2 + 0] + bias[col];
                    float v1 = acc[mt][nt][half * 2 + 1] + bias[col + 1];
                    if (RELU) {
                        v0 = round_tf32(fmaxf(v0, 0.f));
                        v1 = round_tf32(fmaxf(v1, 0.f));
                    }
                    *reinterpret_cast<float2*>(crow + col) = make_float2(v0, v1);
                }
            }
        }
    }
}

// ---------------- softmax + scatter to real token rows ----------------
__global__ __launch_bounds__(256)
void softmax_kernel(float* __restrict__ out) {
    const int i   = blockIdx.x;
    const int tok = g_perm[i];
    const float* lrow = g_logits + (size_t)i * VDIM;
    float*       orow = out + (size_t)tok * VDIM;
    const int tid = threadIdx.x;

    float v[8];
    float mx = -1e30f;
    #pragma unroll
    for (int j = 0; j < 8; j++) {
        v[j] = lrow[tid + 256 * j];
        mx = fmaxf(mx, v[j]);
    }
    #pragma unroll
    for (int o = 16; o; o >>= 1) mx = fmaxf(mx, __shfl_xor_sync(0xffffffffu, mx, o));

    __shared__ float sred[8];
    const int w = tid >> 5;
    if ((tid & 31) == 0) sred[w] = mx;
    __syncthreads();
    float bmx = sred[0];
    #pragma unroll
    for (int j = 1; j < 8; j++) bmx = fmaxf(bmx, sred[j]);

    float s = 0.f;
    #pragma unroll
    for (int j = 0; j < 8; j++) {
        v[j] = expf(v[j] - bmx);
        s += v[j];
    }
    #pragma unroll
    for (int o = 16; o; o >>= 1) s += __shfl_xor_sync(0xffffffffu, s, o);
    __syncthreads();
    if ((tid & 31) == 0) sred[w] = s;
    __syncthreads();
    float tot = 0.f;
    #pragma unroll
    for (int j = 0; j < 8; j++) tot += sred[j];
    const float inv = 1.f / tot;
    #pragma unroll
    for (int j = 0; j < 8; j++) orow[tid + 256 * j] = v[j] * inv;
}

// ---------------- launch ----------------
extern "C" void kernel_launch(void* const* d_in, const int* in_sizes, int n_in,
                              void* d_out, int out_size) {
    const float* e_two     = (const float*)d_in[0];   // [4,1024,768]
    const int*   route_ids = (const int*)d_in[1];     // [4,1024]
    const float* W1        = (const float*)d_in[2];   // [8,768,3072]
    const float* b1        = (const float*)d_in[3];   // [8,3072]
    const float* W2        = (const float*)d_in[4];   // [8,3072,2048]
    const float* b2        = (const float*)d_in[5];   // [8,2048]
    float*       out       = (float*)d_out;           // [4,1024,2048]

    void *pA, *pH, *pL;
    cudaGetSymbolAddress(&pA, g_Aperm);
    cudaGetSymbolAddress(&pH, g_H);
    cudaGetSymbolAddress(&pL, g_logits);

    static bool attr_done = false;
    if (!attr_done) {
        cudaFuncSetAttribute(gemm_dlt<DDIM, FDIM, true>,
                             cudaFuncAttributeMaxDynamicSharedMemorySize, SMEM_BYTES);
        cudaFuncSetAttribute(gemm_dlt<FDIM, VDIM, false>,
                             cudaFuncAttributeMaxDynamicSharedMemorySize, SMEM_BYTES);
        attr_done = true;
    }

    bucket_kernel<<<1, 512>>>(route_ids);
    gather_kernel<<<TOK, 192>>>(e_two);

    dim3 g1(FDIM / 128, TOK / 128, RNUM);   // (24, 32, 8)
    gemm_dlt<DDIM, FDIM, true><<<g1, 128, SMEM_BYTES>>>(
        (const float*)pA, W1, b1, (float*)pH);

    dim3 g2(VDIM / 128, TOK / 128, RNUM);   // (16, 32, 8)
    gemm_dlt<FDIM, VDIM, false><<<g2, 128, SMEM_BYTES>>>(
        (const float*)pH, W2, b2, (float*)pL);

    softmax_kernel<<<TOK, 256>>>(out);
}